// round 4
// baseline (speedup 1.0000x reference)
#include <cuda_runtime.h>
#include <cstdint>

// Problem constants
#define PTOT   8192        // B*H*W points
#define NCODES 16384
#define DIM    256
#define ZELEMS 2097152     // 8*256*32*32

// Scratch (static device globals; no allocations allowed)
__device__ float g_a[PTOT];          // sequential fp32 ||z_row||^2
__device__ int   g_idx[PTOT];
__device__ float g_part[2048];

// ---------------------------------------------------------------------------
// Kernel A: a_p = sum_c fl(z^2), strictly sequential fp32, no FMA contraction.
// ---------------------------------------------------------------------------
__global__ void a_kernel(const float* __restrict__ z) {
    int p = blockIdx.x * 256 + threadIdx.x;
    int b = p >> 10, hw = p & 1023;
    const float* zp = z + (size_t)b * (DIM * 1024) + hw;
    float acc = 0.f;
    #pragma unroll 8
    for (int c = 0; c < DIM; c++) {
        float v = zp[(size_t)c * 1024];
        acc = __fadd_rn(acc, __fmul_rn(v, v));
    }
    g_a[p] = acc;
}

// ---------------------------------------------------------------------------
// Kernel B: fused TF32 GEMM + per-row top-2 tracking + fp64 refine + argmin.
// mma.sync.m16n8k8.row.col.f32.tf32.tf32.f32
// Block 256 thr = 8 warps (2M x 4N). M-tile 64 rows (z persistent in smem),
// N swept over all 16384 codes in 256-chunks, K=256 in 32-chunks, dbl-buffered.
// Selection margin covers d-quantization (~3.1e-5) + tf32 error (~1e-5).
// ---------------------------------------------------------------------------
#define ZS_STRIDE 260           // 256 + 4 pad (words)
#define ES_STRIDE 36            // 32 + 4 pad (words)
#define ZS_WORDS (64 * ZS_STRIDE)
#define ES_WORDS (256 * ES_STRIDE)
#define GEMM_SMEM ((ZS_WORDS + 2 * ES_WORDS) * 4)
#define MARGIN 1.2e-4f
#define MAXC 16

__device__ __forceinline__ void mma_tf32(float c[4],
                                         uint32_t a0, uint32_t a1, uint32_t a2, uint32_t a3,
                                         uint32_t b0, uint32_t b1) {
    asm volatile(
        "mma.sync.aligned.m16n8k8.row.col.f32.tf32.tf32.f32 "
        "{%0,%1,%2,%3}, {%4,%5,%6,%7}, {%8,%9}, {%0,%1,%2,%3};\n"
        : "+f"(c[0]), "+f"(c[1]), "+f"(c[2]), "+f"(c[3])
        : "r"(a0), "r"(a1), "r"(a2), "r"(a3), "r"(b0), "r"(b1));
}

__global__ __launch_bounds__(256, 1)
void gemm_argmin_kernel(const float* __restrict__ z,
                        const float* __restrict__ e) {
    extern __shared__ float smem[];
    float* zs = smem;                  // [64][ZS_STRIDE]
    float* es = smem + ZS_WORDS;       // [2][256][ES_STRIDE]
    const uint32_t* zs_u = reinterpret_cast<const uint32_t*>(zs);

    const int tid  = threadIdx.x;
    const int wid  = tid >> 5, lane = tid & 31;
    const int g    = lane >> 2, tig = lane & 3;
    const int wm   = wid & 1;          // warp row block (2 x 32 rows)
    const int wn   = wid >> 1;         // warp col block (4 x 64 cols)

    const int row0 = blockIdx.x * 64;
    const int b    = row0 >> 10;
    const int hw0  = row0 & 1023;
    const float* zbase = z + (size_t)b * (DIM * 1024) + hw0;

    // Load z tile: zs[r][c] = z[b, c, hw0 + r]
    for (int i = tid; i < 64 * 256; i += 256) {
        int c = i >> 6, r = i & 63;
        zs[r * ZS_STRIDE + c] = zbase[(size_t)c * 1024 + r];
    }
    __syncthreads();

    const float4* eg = reinterpret_cast<const float4*>(e);
    const int q  = tid & 7;            // float4 slot within K-chunk
    const int n0 = tid >> 3;           // 0..31 code group

    const int arow[2] = { (wm * 32 + 0 * 16 + g) * ZS_STRIDE,
                          (wm * 32 + 1 * 16 + g) * ZS_STRIDE };
    int bbase[8];
    #pragma unroll
    for (int ns = 0; ns < 8; ns++)
        bbase[ns] = (wn * 64 + ns * 8 + g) * ES_STRIDE;

    // Per-thread top-2 for the 4 rows this thread's fragments cover.
    // row index ri = ms*2 + half -> physical row wm*32 + ms*16 + g + half*8
    float t1v[4], t2v[4];
    int   t1n[4], t2n[4];
    #pragma unroll
    for (int i = 0; i < 4; i++) { t1v[i] = t2v[i] = -3.4e38f; t1n[i] = t2n[i] = 0; }

    for (int nb = 0; nb < NCODES; nb += 256) {
        float c[2][8][4];
        #pragma unroll
        for (int ms = 0; ms < 2; ms++)
            #pragma unroll
            for (int ns = 0; ns < 8; ns++)
                #pragma unroll
                for (int j = 0; j < 4; j++) c[ms][ns][j] = 0.f;

        // preload K-chunk 0 into buffer 0
        {
            float4 pf[8];
            #pragma unroll
            for (int p = 0; p < 8; p++)
                pf[p] = eg[(size_t)(nb + n0 + 32 * p) * 64 + q];
            #pragma unroll
            for (int p = 0; p < 8; p++)
                *reinterpret_cast<float4*>(&es[(n0 + 32 * p) * ES_STRIDE + 4 * q]) = pf[p];
        }
        __syncthreads();

        #pragma unroll
        for (int kc = 0; kc < 8; kc++) {
            float4 pf[8];
            if (kc < 7) {
                #pragma unroll
                for (int p = 0; p < 8; p++)
                    pf[p] = eg[(size_t)(nb + n0 + 32 * p) * 64 + (kc + 1) * 8 + q];
            }

            const uint32_t* eb = reinterpret_cast<const uint32_t*>(es + (kc & 1) * ES_WORDS);
            const int kzb = kc * 32;

            #pragma unroll
            for (int ks = 0; ks < 4; ks++) {
                const int kk = ks * 8;
                uint32_t a[2][4];
                #pragma unroll
                for (int ms = 0; ms < 2; ms++) {
                    a[ms][0] = zs_u[arow[ms] + kzb + kk + tig];
                    a[ms][1] = zs_u[arow[ms] + 8 * ZS_STRIDE + kzb + kk + tig];
                    a[ms][2] = zs_u[arow[ms] + kzb + kk + tig + 4];
                    a[ms][3] = zs_u[arow[ms] + 8 * ZS_STRIDE + kzb + kk + tig + 4];
                }
                #pragma unroll
                for (int ns = 0; ns < 8; ns++) {
                    uint32_t b0 = eb[bbase[ns] + kk + tig];
                    uint32_t b1 = eb[bbase[ns] + kk + tig + 4];
                    mma_tf32(c[0][ns], a[0][0], a[0][1], a[0][2], a[0][3], b0, b1);
                    mma_tf32(c[1][ns], a[1][0], a[1][1], a[1][2], a[1][3], b0, b1);
                }
            }

            if (kc < 7) {
                float* wb = es + ((kc + 1) & 1) * ES_WORDS;
                #pragma unroll
                for (int p = 0; p < 8; p++)
                    *reinterpret_cast<float4*>(&wb[(n0 + 32 * p) * ES_STRIDE + 4 * q]) = pf[p];
            }
            __syncthreads();
        }

        // ---- top-2 update (gated: only if this tile can improve any row) ----
        float tmax = c[0][0][0];
        #pragma unroll
        for (int ms = 0; ms < 2; ms++)
            #pragma unroll
            for (int ns = 0; ns < 8; ns++)
                #pragma unroll
                for (int j = 0; j < 4; j++) tmax = fmaxf(tmax, c[ms][ns][j]);
        float gate = fminf(fminf(t2v[0], t2v[1]), fminf(t2v[2], t2v[3]));

        if (__any_sync(0xffffffffu, tmax > gate)) {
            #pragma unroll
            for (int ms = 0; ms < 2; ms++)
                #pragma unroll
                for (int half = 0; half < 2; half++) {
                    const int ri = ms * 2 + half;
                    #pragma unroll
                    for (int ns = 0; ns < 8; ns++)
                        #pragma unroll
                        for (int j = 0; j < 2; j++) {
                            float v = c[ms][ns][half * 2 + j];
                            int   n = nb + wn * 64 + ns * 8 + 2 * tig + j;
                            if (v > t2v[ri]) {
                                if (v > t1v[ri]) {
                                    t2v[ri] = t1v[ri]; t2n[ri] = t1n[ri];
                                    t1v[ri] = v;       t1n[ri] = n;
                                } else {
                                    t2v[ri] = v; t2n[ri] = n;
                                }
                            }
                        }
                }
        }
    }

    // ---- reduce top-2 keys across the 16 owner threads per row ----
    __syncthreads();                       // es no longer needed; reuse
    float* kf = es;                        // [64][32] values
    int*   ki = reinterpret_cast<int*>(es + 64 * 32);  // [64][32] indices

    #pragma unroll
    for (int ms = 0; ms < 2; ms++)
        #pragma unroll
        for (int half = 0; half < 2; half++) {
            const int ri = ms * 2 + half;
            const int rl = wm * 32 + ms * 16 + g + half * 8;
            const int o  = (wn * 4 + tig) * 2;
            kf[rl * 32 + o]     = t1v[ri];  ki[rl * 32 + o]     = t1n[ri];
            kf[rl * 32 + o + 1] = t2v[ri];  ki[rl * 32 + o + 1] = t2n[ri];
        }
    __syncthreads();

    // ---- per-row refine: fp64 recompute of candidates, reference rounding ----
    if (tid < 64) {
        const int rl = tid;
        float vt = -3.4e38f;
        #pragma unroll 8
        for (int j = 0; j < 32; j++) vt = fmaxf(vt, kf[rl * 32 + j]);
        const float thr = vt - MARGIN;

        int cand[MAXC]; int cnt = 0;
        #pragma unroll 8
        for (int j = 0; j < 32; j++)
            if (kf[rl * 32 + j] > thr && cnt < MAXC) cand[cnt++] = ki[rl * 32 + j];

        const float a = g_a[row0 + rl];
        float bd = 3.4e38f; int bn = 0x7fffffff;
        for (int ci = 0; ci < cnt; ci++) {
            const int n = cand[ci];
            const float* er = e + (size_t)n * DIM;
            double acc0 = 0.0, acc1 = 0.0;
            #pragma unroll 8
            for (int cc = 0; cc < DIM; cc += 2) {
                acc0 += (double)zs[rl * ZS_STRIDE + cc]     * (double)er[cc];
                acc1 += (double)zs[rl * ZS_STRIDE + cc + 1] * (double)er[cc + 1];
            }
            float y32 = (float)(acc0 + acc1);
            float d = __fsub_rn(a, __fmul_rn(2.0f, y32));
            if (d < bd || (d == bd && n < bn)) { bd = d; bn = n; }
        }
        g_idx[row0 + rl] = bn;
    }
}

// ---------------------------------------------------------------------------
// Kernel C: gather + straight-through rounding emulation + partial loss sums.
// Reference: out = fl(zb + fl(z_q - zb)); loss uses fl(z_q - zb)^2.
// ---------------------------------------------------------------------------
__global__ void gather_loss_kernel(const float* __restrict__ z,
                                   const float* __restrict__ e,
                                   float* __restrict__ out) {
    __shared__ float red[256];
    float acc = 0.f;
    for (int i = blockIdx.x * 256 + threadIdx.x; i < ZELEMS; i += 2048 * 256) {
        int bidx = i >> 18;
        int c    = (i >> 10) & 255;
        int hw   = i & 1023;
        int n    = g_idx[(bidx << 10) | hw];
        float v  = e[(size_t)n * DIM + c];
        float zb = z[i];
        float d  = __fsub_rn(v, zb);
        out[i]   = __fadd_rn(zb, d);
        acc += d * d;
    }
    red[threadIdx.x] = acc;
    __syncthreads();
    for (int s = 128; s; s >>= 1) {
        if (threadIdx.x < s) red[threadIdx.x] += red[threadIdx.x + s];
        __syncthreads();
    }
    if (threadIdx.x == 0) g_part[blockIdx.x] = red[0];
}

// ---------------------------------------------------------------------------
// Kernel D: final loss. loss = (BETA + 1) * mean = 2 * sum / ZELEMS
// ---------------------------------------------------------------------------
__global__ void loss_kernel(float* __restrict__ out, int out_size) {
    __shared__ float red[256];
    float acc = 0.f;
    for (int t = threadIdx.x; t < 2048; t += 256) acc += g_part[t];
    red[threadIdx.x] = acc;
    __syncthreads();
    for (int s = 128; s; s >>= 1) {
        if (threadIdx.x < s) red[threadIdx.x] += red[threadIdx.x + s];
        __syncthreads();
    }
    if (threadIdx.x == 0 && out_size > ZELEMS)
        out[ZELEMS] = 2.0f * red[0] / (float)ZELEMS;
}

// ---------------------------------------------------------------------------
extern "C" void kernel_launch(void* const* d_in, const int* in_sizes, int n_in,
                              void* d_out, int out_size) {
    const float* z = (const float*)d_in[0];   // (8,256,32,32) f32
    const float* e = (const float*)d_in[1];   // (16384,256)   f32
    float* out = (float*)d_out;

    cudaFuncSetAttribute(gemm_argmin_kernel,
                         cudaFuncAttributeMaxDynamicSharedMemorySize, GEMM_SMEM);

    a_kernel<<<PTOT / 256, 256>>>(z);
    gemm_argmin_kernel<<<PTOT / 64, 256, GEMM_SMEM>>>(z, e);
    gather_loss_kernel<<<2048, 256>>>(z, e, out);
    loss_kernel<<<1, 256>>>(out, out_size);
}

// round 8
// speedup vs baseline: 1.4537x; 1.4537x over previous
#include <cuda_runtime.h>
#include <cuda_bf16.h>
#include <cstdint>

// Problem constants
#define PTOT   8192        // B*H*W points
#define NCODES 16384
#define DIM    256
#define ZELEMS 2097152     // 8*256*32*32

// Scratch (static device globals; no allocations allowed)
__device__ float          g_a[PTOT];          // sequential fp32 ||z_row||^2
__device__ int            g_idx[PTOT];
__device__ float          g_part[2048];
__device__ __nv_bfloat16  g_ebf[(size_t)NCODES * DIM];     // codebook bf16
__device__ __nv_bfloat16  g_ybf[(size_t)PTOT * NCODES];    // 256 MB y matrix (bf16)

// ---------------------------------------------------------------------------
// Kernel: e -> bf16
// ---------------------------------------------------------------------------
__global__ void conv_e_kernel(const float* __restrict__ e) {
    size_t i = ((size_t)blockIdx.x * 256 + threadIdx.x) * 8;
    float4 v0 = *reinterpret_cast<const float4*>(e + i);
    float4 v1 = *reinterpret_cast<const float4*>(e + i + 4);
    __nv_bfloat162 h[4];
    h[0] = __nv_bfloat162(__float2bfloat16(v0.x), __float2bfloat16(v0.y));
    h[1] = __nv_bfloat162(__float2bfloat16(v0.z), __float2bfloat16(v0.w));
    h[2] = __nv_bfloat162(__float2bfloat16(v1.x), __float2bfloat16(v1.y));
    h[3] = __nv_bfloat162(__float2bfloat16(v1.z), __float2bfloat16(v1.w));
    *reinterpret_cast<uint4*>(g_ebf + i) = *reinterpret_cast<uint4*>(h);
}

// ---------------------------------------------------------------------------
// Kernel A: a_p = sum_c fl(z^2), strictly sequential fp32, no FMA contraction.
// ---------------------------------------------------------------------------
__global__ void a_kernel(const float* __restrict__ z) {
    int p = blockIdx.x * 256 + threadIdx.x;
    int b = p >> 10, hw = p & 1023;
    const float* zp = z + (size_t)b * (DIM * 1024) + hw;
    float acc = 0.f;
    #pragma unroll 8
    for (int c = 0; c < DIM; c++) {
        float v = zp[(size_t)c * 1024];
        acc = __fadd_rn(acc, __fmul_rn(v, v));
    }
    g_a[p] = acc;
}

// ---------------------------------------------------------------------------
// Kernel B: BF16 tensor-core GEMM  y = z . E^T  (selection pass, y in bf16).
// mma.sync.m16n8k16.row.col.f32.bf16.bf16.f32
// Block 256 thr = 8 warps (2M x 4N). M-tile 64, N-tile 256, K=256 in
// 32-chunks, double buffered with register prefetch.
// ---------------------------------------------------------------------------
#define ZS_WSTRIDE 132          // z row stride in words (264 halves = 256 + 8 pad)
#define ES_WSTRIDE 20           // E row stride in words (40 halves = 32 + 8 pad)
#define ZS_WORDS (64 * ZS_WSTRIDE)          // 8448 words
#define ES_WORDS (256 * ES_WSTRIDE)         // 5120 words per buffer
#define GEMM_SMEM ((ZS_WORDS + 2 * ES_WORDS) * 4)

__device__ __forceinline__ void mma_bf16(float c[4],
                                         uint32_t a0, uint32_t a1, uint32_t a2, uint32_t a3,
                                         uint32_t b0, uint32_t b1) {
    asm volatile(
        "mma.sync.aligned.m16n8k16.row.col.f32.bf16.bf16.f32 "
        "{%0,%1,%2,%3}, {%4,%5,%6,%7}, {%8,%9}, {%0,%1,%2,%3};\n"
        : "+f"(c[0]), "+f"(c[1]), "+f"(c[2]), "+f"(c[3])
        : "r"(a0), "r"(a1), "r"(a2), "r"(a3), "r"(b0), "r"(b1));
}

__global__ __launch_bounds__(256, 1)
void gemm_mma_kernel(const float* __restrict__ z) {
    extern __shared__ uint32_t smem[];
    uint32_t* zs_u = smem;                    // [64][ZS_WSTRIDE] words (bf16 pairs)
    uint32_t* es_u = smem + ZS_WORDS;         // [2][256][ES_WSTRIDE]
    __nv_bfloat16* zs_h = reinterpret_cast<__nv_bfloat16*>(zs_u);

    const int tid  = threadIdx.x;
    const int wid  = tid >> 5, lane = tid & 31;
    const int g    = lane >> 2, tig = lane & 3;
    const int wm   = wid & 1;          // warp row block (2 x 32 rows)
    const int wn   = wid >> 1;         // warp col block (4 x 64 cols)

    const int row0 = blockIdx.x * 64;
    const int b    = row0 >> 10;
    const int hw0  = row0 & 1023;
    const float* zbase = z + (size_t)b * (DIM * 1024) + hw0;

    // Load z tile as bf16: zs[r][c] = bf16(z[b, c, hw0 + r])
    for (int i = tid; i < 64 * 256; i += 256) {
        int c = i >> 6, r = i & 63;
        zs_h[r * 264 + c] = __float2bfloat16(zbase[(size_t)c * 1024 + r]);
    }
    __syncthreads();

    const uint4* eg = reinterpret_cast<const uint4*>(g_ebf);   // 32 uint4 per code row
    const int q  = tid & 3;            // uint4 slot within 32-k chunk (64B)
    const int n0 = tid >> 2;           // 0..63 code group

    const int arow[2] = { (wm * 32 + 0 * 16 + g) * ZS_WSTRIDE,
                          (wm * 32 + 1 * 16 + g) * ZS_WSTRIDE };
    int bbase[8];
    #pragma unroll
    for (int ns = 0; ns < 8; ns++)
        bbase[ns] = (wn * 64 + ns * 8 + g) * ES_WSTRIDE;

    for (int nb = 0; nb < NCODES; nb += 256) {
        float c[2][8][4];
        #pragma unroll
        for (int ms = 0; ms < 2; ms++)
            #pragma unroll
            for (int ns = 0; ns < 8; ns++)
                #pragma unroll
                for (int j = 0; j < 4; j++) c[ms][ns][j] = 0.f;

        // preload K-chunk 0 into buffer 0
        {
            uint4 pf[4];
            #pragma unroll
            for (int p = 0; p < 4; p++)
                pf[p] = eg[(size_t)(nb + n0 + 64 * p) * 32 + q];
            #pragma unroll
            for (int p = 0; p < 4; p++)
                *reinterpret_cast<uint4*>(&es_u[(n0 + 64 * p) * ES_WSTRIDE + 4 * q]) = pf[p];
        }
        __syncthreads();

        #pragma unroll
        for (int kc = 0; kc < 8; kc++) {
            uint4 pf[4];
            if (kc < 7) {
                #pragma unroll
                for (int p = 0; p < 4; p++)
                    pf[p] = eg[(size_t)(nb + n0 + 64 * p) * 32 + (kc + 1) * 4 + q];
            }

            const uint32_t* eb = es_u + (kc & 1) * ES_WORDS;
            const int kwb = kc * 16;     // chunk offset in words

            #pragma unroll
            for (int ks = 0; ks < 2; ks++) {
                const int kw = kwb + ks * 8;     // k-step offset in words (16 halves)
                uint32_t a[2][4];
                #pragma unroll
                for (int ms = 0; ms < 2; ms++) {
                    a[ms][0] = zs_u[arow[ms] + kw + tig];
                    a[ms][1] = zs_u[arow[ms] + 8 * ZS_WSTRIDE + kw + tig];
                    a[ms][2] = zs_u[arow[ms] + kw + tig + 4];
                    a[ms][3] = zs_u[arow[ms] + 8 * ZS_WSTRIDE + kw + tig + 4];
                }
                const int ksw = ks * 8;
                #pragma unroll
                for (int ns = 0; ns < 8; ns++) {
                    uint32_t b0 = eb[bbase[ns] + ksw + tig];
                    uint32_t b1 = eb[bbase[ns] + ksw + tig + 4];
                    mma_bf16(c[0][ns], a[0][0], a[0][1], a[0][2], a[0][3], b0, b1);
                    mma_bf16(c[1][ns], a[1][0], a[1][1], a[1][2], a[1][3], b0, b1);
                }
            }

            if (kc < 7) {
                uint32_t* wb = es_u + ((kc + 1) & 1) * ES_WORDS;
                #pragma unroll
                for (int p = 0; p < 4; p++)
                    *reinterpret_cast<uint4*>(&wb[(n0 + 64 * p) * ES_WSTRIDE + 4 * q]) = pf[p];
            }
            __syncthreads();
        }

        // Epilogue: y tile -> bf16 stores
        #pragma unroll
        for (int ms = 0; ms < 2; ms++) {
            int r0 = row0 + wm * 32 + ms * 16 + g;
            #pragma unroll
            for (int ns = 0; ns < 8; ns++) {
                int col = nb + wn * 64 + ns * 8 + 2 * tig;
                __nv_bfloat162 lo(__float2bfloat16(c[ms][ns][0]), __float2bfloat16(c[ms][ns][1]));
                __nv_bfloat162 hi(__float2bfloat16(c[ms][ns][2]), __float2bfloat16(c[ms][ns][3]));
                *reinterpret_cast<__nv_bfloat162*>(&g_ybf[(size_t)r0 * NCODES + col]) = lo;
                *reinterpret_cast<__nv_bfloat162*>(&g_ybf[(size_t)(r0 + 8) * NCODES + col]) = hi;
            }
        }
    }
}

// ---------------------------------------------------------------------------
// Kernel C: per row, y_max + contenders (y > y_max - margin), fp64 recompute,
// reference rounding d = fl(a - fl(2 * fl32(y_exact))), first-index ties.
// Margin covers d-bin (3.1e-5) + bf16 mma error (~2e-5) + bf16 y store (4e-6).
// ---------------------------------------------------------------------------
#define MARGIN 1.2e-4f
#define MAXCAND 64

__global__ void refine_kernel(const float* __restrict__ z,
                              const float* __restrict__ e) {
    __shared__ float s_z[256];
    __shared__ float s_red[256];
    __shared__ int   s_cand[MAXCAND];
    __shared__ float s_d[MAXCAND];
    __shared__ int   s_cnt;

    const int p = blockIdx.x;
    const int b = p >> 10, hw = p & 1023;
    const int t = threadIdx.x;

    s_z[t] = z[(size_t)b * (DIM * 1024) + (size_t)t * 1024 + hw];
    if (t == 0) s_cnt = 0;

    const __nv_bfloat162* yrow = reinterpret_cast<const __nv_bfloat162*>(
        g_ybf + (size_t)p * NCODES);
    float m = -3.4e38f;
    #pragma unroll 4
    for (int k = t; k < NCODES / 2; k += 256) {
        float2 v = __bfloat1622float2(yrow[k]);
        m = fmaxf(m, fmaxf(v.x, v.y));
    }
    s_red[t] = m;
    __syncthreads();
    for (int s = 128; s; s >>= 1) {
        if (t < s) s_red[t] = fmaxf(s_red[t], s_red[t + s]);
        __syncthreads();
    }
    const float thr = s_red[0] - MARGIN;

    #pragma unroll 4
    for (int k = t; k < NCODES / 2; k += 256) {
        float2 v = __bfloat1622float2(yrow[k]);
        if (v.x > thr) {
            int slot = atomicAdd(&s_cnt, 1);
            if (slot < MAXCAND) s_cand[slot] = 2 * k;
        }
        if (v.y > thr) {
            int slot = atomicAdd(&s_cnt, 1);
            if (slot < MAXCAND) s_cand[slot] = 2 * k + 1;
        }
    }
    __syncthreads();

    const int cnt = min(s_cnt, MAXCAND);
    const float a = g_a[p];
    const int wid = t >> 5, lane = t & 31;

    for (int ci = wid; ci < cnt; ci += 8) {
        const float* er = e + (size_t)s_cand[ci] * DIM;
        double acc = 0.0;
        #pragma unroll
        for (int j = 0; j < 8; j++) {
            int cc = lane + 32 * j;
            acc += (double)s_z[cc] * (double)er[cc];
        }
        #pragma unroll
        for (int mlt = 16; mlt; mlt >>= 1)
            acc += __shfl_xor_sync(0xffffffffu, acc, mlt);
        if (lane == 0) {
            float y32 = (float)acc;
            s_d[ci] = __fsub_rn(a, __fmul_rn(2.0f, y32));
        }
    }
    __syncthreads();

    if (t == 0) {
        float bd = 3.4e38f; int bn = 0x7fffffff;
        for (int ci = 0; ci < cnt; ci++) {
            float d = s_d[ci]; int n = s_cand[ci];
            if (d < bd || (d == bd && n < bn)) { bd = d; bn = n; }
        }
        g_idx[p] = bn;
    }
}

// ---------------------------------------------------------------------------
// Kernel D: gather + straight-through rounding emulation + partial loss sums.
// ---------------------------------------------------------------------------
__global__ void gather_loss_kernel(const float* __restrict__ z,
                                   const float* __restrict__ e,
                                   float* __restrict__ out) {
    __shared__ float red[256];
    float acc = 0.f;
    for (int i = blockIdx.x * 256 + threadIdx.x; i < ZELEMS; i += 2048 * 256) {
        int bidx = i >> 18;
        int c    = (i >> 10) & 255;
        int hw   = i & 1023;
        int n    = g_idx[(bidx << 10) | hw];
        float v  = e[(size_t)n * DIM + c];
        float zb = z[i];
        float d  = __fsub_rn(v, zb);
        out[i]   = __fadd_rn(zb, d);
        acc += d * d;
    }
    red[threadIdx.x] = acc;
    __syncthreads();
    for (int s = 128; s; s >>= 1) {
        if (threadIdx.x < s) red[threadIdx.x] += red[threadIdx.x + s];
        __syncthreads();
    }
    if (threadIdx.x == 0) g_part[blockIdx.x] = red[0];
}

// ---------------------------------------------------------------------------
// Kernel E: final loss. loss = (BETA + 1) * mean = 2 * sum / ZELEMS
// ---------------------------------------------------------------------------
__global__ void loss_kernel(float* __restrict__ out, int out_size) {
    __shared__ float red[256];
    float acc = 0.f;
    for (int t = threadIdx.x; t < 2048; t += 256) acc += g_part[t];
    red[threadIdx.x] = acc;
    __syncthreads();
    for (int s = 128; s; s >>= 1) {
        if (threadIdx.x < s) red[threadIdx.x] += red[threadIdx.x + s];
        __syncthreads();
    }
    if (threadIdx.x == 0 && out_size > ZELEMS)
        out[ZELEMS] = 2.0f * red[0] / (float)ZELEMS;
}

// ---------------------------------------------------------------------------
extern "C" void kernel_launch(void* const* d_in, const int* in_sizes, int n_in,
                              void* d_out, int out_size) {
    const float* z = (const float*)d_in[0];   // (8,256,32,32) f32
    const float* e = (const float*)d_in[1];   // (16384,256)   f32
    float* out = (float*)d_out;

    cudaFuncSetAttribute(gemm_mma_kernel,
                         cudaFuncAttributeMaxDynamicSharedMemorySize, GEMM_SMEM);

    conv_e_kernel<<<2048, 256>>>(e);
    a_kernel<<<PTOT / 256, 256>>>(z);
    gemm_mma_kernel<<<PTOT / 64, 256, GEMM_SMEM>>>(z);
    refine_kernel<<<PTOT, 256>>>(z, e);
    gather_loss_kernel<<<2048, 256>>>(z, e, out);
    loss_kernel<<<1, 256>>>(out, out_size);
}